// round 1
// baseline (speedup 1.0000x reference)
#include <cuda_runtime.h>
#include <math.h>

#define S_LEN  2048
#define HID    3584
#define NHEADS 28
#define NKV    4
#define HDIM   128
#define KVDIM  512      // NKV * HDIM
#define GROUPS 7        // NHEADS / NKV

// ---------------- scratch (allocation-free) ----------------
__device__ float g_Q [S_LEN * HID];
__device__ float g_K [S_LEN * KVDIM];
__device__ float g_V [S_LEN * KVDIM];
__device__ float g_AO[S_LEN * HID];

// ============================================================
// GEMM: C[M,N] = A[M,K] @ B[N,K]^T + bias[N]   (both row-major, K contiguous)
// 128x128 tile, BK=8, 256 threads, 8x8 per-thread register tile.
// ============================================================
__global__ void __launch_bounds__(256)
gemm_nt(const float* __restrict__ A, const float* __restrict__ B,
        const float* __restrict__ bias, float* __restrict__ C,
        int M, int N, int K)
{
    __shared__ float As[8][128];
    __shared__ float Bs[8][128];

    const int tid  = threadIdx.x;
    const int m0   = blockIdx.y * 128;
    const int n0   = blockIdx.x * 128;
    const int tx   = tid & 15;
    const int ty   = tid >> 4;
    const int lrow = tid >> 1;
    const int lk   = (tid & 1) << 2;

    const float* Ap = A + (size_t)(m0 + lrow) * K + lk;
    const float* Bp = B + (size_t)(n0 + lrow) * K + lk;

    float acc[8][8];
#pragma unroll
    for (int i = 0; i < 8; i++)
#pragma unroll
        for (int j = 0; j < 8; j++) acc[i][j] = 0.0f;

    for (int k0 = 0; k0 < K; k0 += 8) {
        float4 av = *(const float4*)(Ap + k0);
        float4 bv = *(const float4*)(Bp + k0);
        As[lk + 0][lrow] = av.x; As[lk + 1][lrow] = av.y;
        As[lk + 2][lrow] = av.z; As[lk + 3][lrow] = av.w;
        Bs[lk + 0][lrow] = bv.x; Bs[lk + 1][lrow] = bv.y;
        Bs[lk + 2][lrow] = bv.z; Bs[lk + 3][lrow] = bv.w;
        __syncthreads();

#pragma unroll
        for (int kk = 0; kk < 8; kk++) {
            float4 a0 = *(const float4*)&As[kk][ty * 8];
            float4 a1 = *(const float4*)&As[kk][ty * 8 + 4];
            float4 b0 = *(const float4*)&Bs[kk][tx * 8];
            float4 b1 = *(const float4*)&Bs[kk][tx * 8 + 4];
            float a[8] = {a0.x, a0.y, a0.z, a0.w, a1.x, a1.y, a1.z, a1.w};
            float b[8] = {b0.x, b0.y, b0.z, b0.w, b1.x, b1.y, b1.z, b1.w};
#pragma unroll
            for (int i = 0; i < 8; i++)
#pragma unroll
                for (int j = 0; j < 8; j++)
                    acc[i][j] = fmaf(a[i], b[j], acc[i][j]);
        }
        __syncthreads();
    }

    float bb[8];
#pragma unroll
    for (int j = 0; j < 8; j++)
        bb[j] = bias ? bias[n0 + tx * 8 + j] : 0.0f;

#pragma unroll
    for (int i = 0; i < 8; i++) {
        float* crow = C + (size_t)(m0 + ty * 8 + i) * N + n0 + tx * 8;
        float4 o0, o1;
        o0.x = acc[i][0] + bb[0]; o0.y = acc[i][1] + bb[1];
        o0.z = acc[i][2] + bb[2]; o0.w = acc[i][3] + bb[3];
        o1.x = acc[i][4] + bb[4]; o1.y = acc[i][5] + bb[5];
        o1.z = acc[i][6] + bb[6]; o1.w = acc[i][7] + bb[7];
        *(float4*)(crow)     = o0;
        *(float4*)(crow + 4) = o1;
    }
}

// ============================================================
// RoPE applied in-place to g_Q (28 heads) and g_K (4 heads).
// grid = (S_LEN, 32), block = 64 (one thread per rotation pair).
// Angles in double to be immune to fast-math range reduction.
// ============================================================
__global__ void rope_kernel(const int* __restrict__ pos_ids)
{
    const int s = blockIdx.x;
    const int h = blockIdx.y;
    const int i = threadIdx.x;   // 0..63

    double inv = pow(10000.0, -(double)i / 64.0);
    double ang = (double)pos_ids[s] * inv;
    float c  = (float)cos(ang);
    float sn = (float)sin(ang);

    float* p;
    if (h < NHEADS) p = g_Q + (size_t)s * HID   + h * HDIM;
    else            p = g_K + (size_t)s * KVDIM + (h - NHEADS) * HDIM;

    float x1 = p[i];
    float x2 = p[i + 64];
    p[i]      = x1 * c - x2 * sn;
    p[i + 64] = x2 * c + x1 * sn;
}

// ============================================================
// Causal GQA flash-attention. One CTA = one head x one 64-row Q tile.
// SMEM: Qs[64][128], Kst[128][64] (transposed K), Vs[64][128],
//       Ss[64][65], m/l/alpha[64].
// ============================================================
#define ATTN_SMEM_FLOATS (64*128 + 128*64 + 64*128 + 64*65 + 192)
#define ATTN_SMEM_BYTES  (ATTN_SMEM_FLOATS * 4)

__global__ void __launch_bounds__(256)
attn_kernel()
{
    extern __shared__ float sm[];
    float* Qs   = sm;                 // 64*128
    float* Kst  = Qs  + 64 * 128;     // 128*64 : Kst[d*64 + n]
    float* Vs   = Kst + 128 * 64;     // 64*128
    float* Ss   = Vs  + 64 * 128;     // 64*65
    float* mrow = Ss  + 64 * 65;      // 64
    float* lrow = mrow + 64;          // 64
    float* arow = lrow + 64;          // 64

    const int qt  = gridDim.x - 1 - blockIdx.x;  // heavy tiles launch first
    const int h   = blockIdx.y;
    const int kvh = h / GROUPS;
    const int tid = threadIdx.x;
    const int qm  = qt * 64;
    const float scale = 0.08838834764831845f;    // 1/sqrt(128)

    // ---- load scaled Q tile ----
#pragma unroll
    for (int t = 0; t < 8; t++) {
        int idx = tid + 256 * t;            // 0..2047 float4 slots
        int r   = idx >> 5;
        int c4  = idx & 31;
        float4 v = *(const float4*)(g_Q + (size_t)(qm + r) * HID + h * HDIM + c4 * 4);
        v.x *= scale; v.y *= scale; v.z *= scale; v.w *= scale;
        *(float4*)(Qs + r * 128 + c4 * 4) = v;
    }

    float acc[32];
#pragma unroll
    for (int z = 0; z < 32; z++) acc[z] = 0.0f;
    const int orow = tid >> 2;
    const int ocg  = tid & 3;

    if (tid < 64) { mrow[tid] = -1e30f; lrow[tid] = 0.0f; }
    __syncthreads();

    const int sx = tid & 15;
    const int sy = tid >> 4;
    const int ntiles = qt + 1;

    for (int kt = 0; kt < ntiles; kt++) {
        const int kn = kt * 64;

        // ---- load K tile transposed: Kst[d][n] ----
#pragma unroll
        for (int t = 0; t < 8; t++) {
            int idx = tid + 256 * t;
            int d4  = idx >> 6;            // 0..31
            int n   = idx & 63;
            float4 v = *(const float4*)(g_K + (size_t)(kn + n) * KVDIM + kvh * HDIM + d4 * 4);
            Kst[(d4 * 4 + 0) * 64 + n] = v.x;
            Kst[(d4 * 4 + 1) * 64 + n] = v.y;
            Kst[(d4 * 4 + 2) * 64 + n] = v.z;
            Kst[(d4 * 4 + 3) * 64 + n] = v.w;
        }
        // ---- load V tile: Vs[r][c] ----
#pragma unroll
        for (int t = 0; t < 8; t++) {
            int idx = tid + 256 * t;
            int r   = idx >> 5;
            int c4  = idx & 31;
            *(float4*)(Vs + r * 128 + c4 * 4) =
                *(const float4*)(g_V + (size_t)(kn + r) * KVDIM + kvh * HDIM + c4 * 4);
        }
        __syncthreads();

        // ---- scores: 4x4 per thread, S = Qs @ Kst ----
        float sacc[4][4];
#pragma unroll
        for (int i = 0; i < 4; i++)
#pragma unroll
            for (int j = 0; j < 4; j++) sacc[i][j] = 0.0f;

#pragma unroll 8
        for (int d = 0; d < 128; d += 4) {
            float4 av[4], bvv[4];
#pragma unroll
            for (int i = 0; i < 4; i++)
                av[i] = *(const float4*)(Qs + (sy * 4 + i) * 128 + d);
#pragma unroll
            for (int e = 0; e < 4; e++)
                bvv[e] = *(const float4*)(Kst + (d + e) * 64 + sx * 4);
#pragma unroll
            for (int i = 0; i < 4; i++) {
                float ae[4] = {av[i].x, av[i].y, av[i].z, av[i].w};
#pragma unroll
                for (int e = 0; e < 4; e++) {
                    sacc[i][0] = fmaf(ae[e], bvv[e].x, sacc[i][0]);
                    sacc[i][1] = fmaf(ae[e], bvv[e].y, sacc[i][1]);
                    sacc[i][2] = fmaf(ae[e], bvv[e].z, sacc[i][2]);
                    sacc[i][3] = fmaf(ae[e], bvv[e].w, sacc[i][3]);
                }
            }
        }

        const bool diag = (kt == qt);
#pragma unroll
        for (int i = 0; i < 4; i++) {
            int qr = sy * 4 + i;
#pragma unroll
            for (int j = 0; j < 4; j++) {
                int kc = sx * 4 + j;
                float v = sacc[i][j];
                if (diag && kc > qr) v = -1e30f;
                Ss[qr * 65 + kc] = v;
            }
        }
        __syncthreads();

        // ---- online softmax (one thread per row) ----
        if (tid < 64) {
            int r = tid;
            float m_old = mrow[r];
            float mx = m_old;
            for (int k = 0; k < 64; k++) mx = fmaxf(mx, Ss[r * 65 + k]);
            float a = expf(m_old - mx);
            float sum = 0.0f;
            for (int k = 0; k < 64; k++) {
                float p = expf(Ss[r * 65 + k] - mx);
                Ss[r * 65 + k] = p;
                sum += p;
            }
            lrow[r] = lrow[r] * a + sum;
            mrow[r] = mx;
            arow[r] = a;
        }
        __syncthreads();

        // ---- rescale + PV: O[r][c] += P[r][k] * V[k][c] ----
        {
            float a = arow[orow];
#pragma unroll
            for (int z = 0; z < 32; z++) acc[z] *= a;
        }
#pragma unroll 4
        for (int kk = 0; kk < 64; kk++) {
            float p = Ss[orow * 65 + kk];
            const float4* vp = (const float4*)(Vs + kk * 128 + ocg * 32);
#pragma unroll
            for (int j4 = 0; j4 < 8; j4++) {
                float4 v = vp[j4];
                acc[j4 * 4 + 0] = fmaf(p, v.x, acc[j4 * 4 + 0]);
                acc[j4 * 4 + 1] = fmaf(p, v.y, acc[j4 * 4 + 1]);
                acc[j4 * 4 + 2] = fmaf(p, v.z, acc[j4 * 4 + 2]);
                acc[j4 * 4 + 3] = fmaf(p, v.w, acc[j4 * 4 + 3]);
            }
        }
        __syncthreads();
    }

    // ---- epilogue ----
    const float inv_l = 1.0f / lrow[orow];
    float* op = g_AO + (size_t)(qm + orow) * HID + h * HDIM + ocg * 32;
#pragma unroll
    for (int j4 = 0; j4 < 8; j4++) {
        float4 o;
        o.x = acc[j4 * 4 + 0] * inv_l;
        o.y = acc[j4 * 4 + 1] * inv_l;
        o.z = acc[j4 * 4 + 2] * inv_l;
        o.w = acc[j4 * 4 + 3] * inv_l;
        *(float4*)(op + j4 * 4) = o;
    }
}

// ============================================================
// launch
// ============================================================
extern "C" void kernel_launch(void* const* d_in, const int* in_sizes, int n_in,
                              void* d_out, int out_size)
{
    const float* hs  = (const float*)d_in[0];
    const int*   pos = (const int*)  d_in[1];
    const float* Wq  = (const float*)d_in[2];
    const float* bq  = (const float*)d_in[3];
    const float* Wk  = (const float*)d_in[4];
    const float* bk  = (const float*)d_in[5];
    const float* Wv  = (const float*)d_in[6];
    const float* bv  = (const float*)d_in[7];
    const float* Wo  = (const float*)d_in[8];
    float* out = (float*)d_out;

    void *qp, *kp, *vp, *aop;
    cudaGetSymbolAddress(&qp,  g_Q);
    cudaGetSymbolAddress(&kp,  g_K);
    cudaGetSymbolAddress(&vp,  g_V);
    cudaGetSymbolAddress(&aop, g_AO);

    cudaFuncSetAttribute(attn_kernel,
                         cudaFuncAttributeMaxDynamicSharedMemorySize,
                         ATTN_SMEM_BYTES);

    // QKV projections
    gemm_nt<<<dim3(HID / 128,   S_LEN / 128), 256>>>(hs, Wq, bq, (float*)qp, S_LEN, HID,   HID);
    gemm_nt<<<dim3(KVDIM / 128, S_LEN / 128), 256>>>(hs, Wk, bk, (float*)kp, S_LEN, KVDIM, HID);
    gemm_nt<<<dim3(KVDIM / 128, S_LEN / 128), 256>>>(hs, Wv, bv, (float*)vp, S_LEN, KVDIM, HID);

    // RoPE on Q and K
    rope_kernel<<<dim3(S_LEN, NHEADS + NKV), 64>>>(pos);

    // causal GQA attention
    attn_kernel<<<dim3(S_LEN / 64, NHEADS), 256, ATTN_SMEM_BYTES>>>();

    // output projection (no bias)
    gemm_nt<<<dim3(HID / 128, S_LEN / 128), 256>>>((const float*)aop, Wo, nullptr, out,
                                                   S_LEN, HID, HID);
}

// round 3
// speedup vs baseline: 1.6665x; 1.6665x over previous
#include <cuda_runtime.h>
#include <cuda_bf16.h>
#include <math.h>
#include <stdint.h>

#define S_LEN  2048
#define HID    3584
#define NHEADS 28
#define NKV    4
#define HDIM   128
#define KVDIM  512
#define GROUPS 7
#define NKB    (HID / 64)   // 56 k-blocks of 64

// ---------------- scratch (allocation-free) ----------------
__device__ float g_Q [S_LEN * HID];
__device__ float g_K [S_LEN * KVDIM];
__device__ float g_V [S_LEN * KVDIM];
__device__ float g_AO[S_LEN * HID];
__device__ float g_cs[S_LEN * 64];
__device__ float g_sn[S_LEN * 64];

// bf16 hi/lo split buffers
__device__ __nv_bfloat16 g_Ah [S_LEN * HID];
__device__ __nv_bfloat16 g_Al [S_LEN * HID];
__device__ __nv_bfloat16 g_AOh[S_LEN * HID];
__device__ __nv_bfloat16 g_AOl[S_LEN * HID];
__device__ __nv_bfloat16 g_Wqh[HID * HID];
__device__ __nv_bfloat16 g_Wql[HID * HID];
__device__ __nv_bfloat16 g_Wkh[KVDIM * HID];
__device__ __nv_bfloat16 g_Wkl[KVDIM * HID];
__device__ __nv_bfloat16 g_Wvh[KVDIM * HID];
__device__ __nv_bfloat16 g_Wvl[KVDIM * HID];
__device__ __nv_bfloat16 g_Woh[HID * HID];
__device__ __nv_bfloat16 g_Wol[HID * HID];

// ============================================================
// helpers
// ============================================================
__device__ __forceinline__ uint32_t smem_u32(const void* p) {
    uint32_t a;
    asm("{ .reg .u64 t; cvta.to.shared.u64 t, %1; cvt.u32.u64 %0, t; }"
        : "=r"(a) : "l"(p));
    return a;
}

__device__ __forceinline__ void ldsm_x4(uint32_t addr, uint32_t* r) {
    asm volatile("ldmatrix.sync.aligned.m8n8.x4.shared.b16 {%0,%1,%2,%3}, [%4];"
                 : "=r"(r[0]), "=r"(r[1]), "=r"(r[2]), "=r"(r[3]) : "r"(addr));
}

__device__ __forceinline__ void mma_bf16(float* c, const uint32_t* a,
                                         const uint32_t* b) {
    asm volatile("mma.sync.aligned.m16n8k16.row.col.f32.bf16.bf16.f32 "
                 "{%0,%1,%2,%3}, {%4,%5,%6,%7}, {%8,%9}, {%0,%1,%2,%3};"
                 : "+f"(c[0]), "+f"(c[1]), "+f"(c[2]), "+f"(c[3])
                 : "r"(a[0]), "r"(a[1]), "r"(a[2]), "r"(a[3]),
                   "r"(b[0]), "r"(b[1]));
}

#define CP_ASYNC16(dst, src) \
    asm volatile("cp.async.cg.shared.global [%0], [%1], 16;" \
                 :: "r"(dst), "l"(src) : "memory")
#define CP_COMMIT() asm volatile("cp.async.commit_group;" ::: "memory")
#define CP_WAIT1()  asm volatile("cp.async.wait_group 1;" ::: "memory")
#define CP_WAIT0()  asm volatile("cp.async.wait_group 0;" ::: "memory")

// ============================================================
// fp32 -> bf16 hi/lo split
// ============================================================
__global__ void cvt_split(const float* __restrict__ src,
                          __nv_bfloat16* __restrict__ hi,
                          __nv_bfloat16* __restrict__ lo, int n4)
{
    int i = blockIdx.x * blockDim.x + threadIdx.x;
    if (i >= n4) return;
    float4 v = ((const float4*)src)[i];
    __nv_bfloat16 h0 = __float2bfloat16(v.x);
    __nv_bfloat16 h1 = __float2bfloat16(v.y);
    __nv_bfloat16 h2 = __float2bfloat16(v.z);
    __nv_bfloat16 h3 = __float2bfloat16(v.w);
    __nv_bfloat162 hh0 = {h0, h1}, hh1 = {h2, h3};
    __nv_bfloat162 ll0, ll1;
    ll0.x = __float2bfloat16(v.x - __bfloat162float(h0));
    ll0.y = __float2bfloat16(v.y - __bfloat162float(h1));
    ll1.x = __float2bfloat16(v.z - __bfloat162float(h2));
    ll1.y = __float2bfloat16(v.w - __bfloat162float(h3));
    ((__nv_bfloat162*)hi)[i * 2]     = hh0;
    ((__nv_bfloat162*)hi)[i * 2 + 1] = hh1;
    ((__nv_bfloat162*)lo)[i * 2]     = ll0;
    ((__nv_bfloat162*)lo)[i * 2 + 1] = ll1;
}

// ============================================================
// HMMA GEMM: C[M,N] = Ahl[M,3584] @ Bhl[N,3584]^T (+bias)
// CTA tile 128x128, BK=64, 8 warps (warp tile 32x64), bf16 3-pass split.
// cp.async double-buffered, XOR-swizzled SMEM, ldmatrix.x4.
// ============================================================
#define GT_TILE 16384              // one 128x64 bf16 tile (128 rows x 128B)
#define GT_BUF  (4 * GT_TILE)      // Ah, Al, Bh, Bl
#define GT_SMEM (2 * GT_BUF)       // double buffer = 128KB

__global__ void __launch_bounds__(256, 1)
hgemm(const __nv_bfloat16* __restrict__ Ah, const __nv_bfloat16* __restrict__ Al,
      const __nv_bfloat16* __restrict__ Bh, const __nv_bfloat16* __restrict__ Bl,
      const float* __restrict__ bias, float* __restrict__ C, int N)
{
    extern __shared__ char smem[];
    const uint32_t sb = smem_u32(smem);
    const int tid    = threadIdx.x;
    const int lane   = tid & 31;
    const int wid    = tid >> 5;
    const int warp_m = wid & 3;        // 4 warps over M (32 rows each)
    const int warp_n = wid >> 2;       // 2 warps over N (64 cols each)
    const int m0 = blockIdx.y * 128;
    const int n0 = blockIdx.x * 128;

    const __nv_bfloat16* gsrc[4] = {
        Ah + (size_t)m0 * HID, Al + (size_t)m0 * HID,
        Bh + (size_t)n0 * HID, Bl + (size_t)n0 * HID };

    const int lr = tid >> 3;         // 0..31  loader base row
    const int lc = tid & 7;          // chunk 0..7

    // issue async loads of k-block kb into buffer buf
    auto issue = [&](int kb, int buf) {
        const uint32_t bufb = sb + buf * GT_BUF;
#pragma unroll
        for (int arr = 0; arr < 4; arr++) {
#pragma unroll
            for (int j = 0; j < 4; j++) {
                int row = lr + 32 * j;
                const __nv_bfloat16* src =
                    gsrc[arr] + (size_t)row * HID + kb * 64 + lc * 8;
                uint32_t dst = bufb + arr * GT_TILE + row * 128 +
                               ((lc ^ (row & 7)) << 4);
                CP_ASYNC16(dst, src);
            }
        }
        CP_COMMIT();
    };

    float c[2][8][4];
#pragma unroll
    for (int i = 0; i < 2; i++)
#pragma unroll
        for (int j = 0; j < 8; j++)
#pragma unroll
            for (int z = 0; z < 4; z++) c[i][j][z] = 0.0f;

    // precompute ldmatrix base offsets (within a tile)
    // A: row = warp_m*32 + mt*16 + (lane&15); chunk = kc + (lane>>4)
    const int a_row  = warp_m * 32 + (lane & 15);
    const int a_csel = lane >> 4;
    // B: row = warp_n*64 + np*16 + (lane&7) + ((lane>>4)<<3); chunk = kc + ((lane>>3)&1)
    const int b_row  = warp_n * 64 + (lane & 7) + ((lane >> 4) << 3);
    const int b_csel = (lane >> 3) & 1;

    issue(0, 0);

    for (int kb = 0; kb < NKB; kb++) {
        if (kb + 1 < NKB) issue(kb + 1, (kb + 1) & 1);
        if (kb + 1 < NKB) { CP_WAIT1(); } else { CP_WAIT0(); }
        __syncthreads();

        const uint32_t bufb = sb + (kb & 1) * GT_BUF;
        const uint32_t tAh = bufb;
        const uint32_t tAl = bufb + GT_TILE;
        const uint32_t tBh = bufb + 2 * GT_TILE;
        const uint32_t tBl = bufb + 3 * GT_TILE;

#pragma unroll
        for (int ks = 0; ks < 4; ks++) {
            const int kc = ks * 2;
            uint32_t ah[2][4], al[2][4], bh[4][4], bl[4][4];
#pragma unroll
            for (int mt = 0; mt < 2; mt++) {
                int row   = a_row + mt * 16;
                int chunk = kc + a_csel;
                uint32_t off = row * 128 + ((chunk ^ (row & 7)) << 4);
                ldsm_x4(tAh + off, ah[mt]);
                ldsm_x4(tAl + off, al[mt]);
            }
#pragma unroll
            for (int np = 0; np < 4; np++) {
                int row   = b_row + np * 16;
                int chunk = kc + b_csel;
                uint32_t off = row * 128 + ((chunk ^ (row & 7)) << 4);
                ldsm_x4(tBh + off, bh[np]);
                ldsm_x4(tBl + off, bl[np]);
            }
#pragma unroll
            for (int mt = 0; mt < 2; mt++) {
#pragma unroll
                for (int nt = 0; nt < 8; nt++) {
                    uint32_t* bhp = &bh[nt >> 1][(nt & 1) * 2];
                    uint32_t* blp = &bl[nt >> 1][(nt & 1) * 2];
                    mma_bf16(c[mt][nt], ah[mt], bhp);
                    mma_bf16(c[mt][nt], ah[mt], blp);
                    mma_bf16(c[mt][nt], al[mt], bhp);
                }
            }
        }
        __syncthreads();
    }

    // epilogue
#pragma unroll
    for (int mt = 0; mt < 2; mt++) {
#pragma unroll
        for (int nt = 0; nt < 8; nt++) {
            int m = m0 + warp_m * 32 + mt * 16 + (lane >> 2);
            int n = n0 + warp_n * 64 + nt * 8 + (lane & 3) * 2;
            float b0 = 0.0f, b1 = 0.0f;
            if (bias) { b0 = bias[n]; b1 = bias[n + 1]; }
            float2 v0 = {c[mt][nt][0] + b0, c[mt][nt][1] + b1};
            float2 v1 = {c[mt][nt][2] + b0, c[mt][nt][3] + b1};
            *(float2*)(C + (size_t)m * N + n)       = v0;
            *(float2*)(C + (size_t)(m + 8) * N + n) = v1;
        }
    }
}

// ============================================================
// RoPE: table + apply
// ============================================================
__global__ void rope_table(const int* __restrict__ pos_ids)
{
    const int s = blockIdx.x;
    const int i = threadIdx.x;    // 0..63
    double inv = pow(10000.0, -(double)i / 64.0);
    double ang = (double)pos_ids[s] * inv;
    g_cs[s * 64 + i] = (float)cos(ang);
    g_sn[s * 64 + i] = (float)sin(ang);
}

__global__ void rope_apply()
{
    const int s = blockIdx.x;
    const int h = blockIdx.y;
    const int i = threadIdx.x;    // 0..63
    float c  = g_cs[s * 64 + i];
    float sn = g_sn[s * 64 + i];
    float* p;
    if (h < NHEADS) p = g_Q + (size_t)s * HID   + h * HDIM;
    else            p = g_K + (size_t)s * KVDIM + (h - NHEADS) * HDIM;
    float x1 = p[i];
    float x2 = p[i + 64];
    p[i]      = x1 * c - x2 * sn;
    p[i + 64] = x2 * c + x1 * sn;
}

// ============================================================
// Causal GQA flash-attention (known correct, fp32 FFMA)
// ============================================================
#define ATTN_SMEM_FLOATS (64*128 + 128*64 + 64*128 + 64*65 + 192)
#define ATTN_SMEM_BYTES  (ATTN_SMEM_FLOATS * 4)

__global__ void __launch_bounds__(256)
attn_kernel()
{
    extern __shared__ float sm[];
    float* Qs   = sm;
    float* Kst  = Qs  + 64 * 128;
    float* Vs   = Kst + 128 * 64;
    float* Ss   = Vs  + 64 * 128;
    float* mrow = Ss  + 64 * 65;
    float* lrow = mrow + 64;
    float* arow = lrow + 64;

    const int qt  = gridDim.x - 1 - blockIdx.x;
    const int h   = blockIdx.y;
    const int kvh = h / GROUPS;
    const int tid = threadIdx.x;
    const int qm  = qt * 64;
    const float scale = 0.08838834764831845f;

#pragma unroll
    for (int t = 0; t < 8; t++) {
        int idx = tid + 256 * t;
        int r   = idx >> 5;
        int c4  = idx & 31;
        float4 v = *(const float4*)(g_Q + (size_t)(qm + r) * HID + h * HDIM + c4 * 4);
        v.x *= scale; v.y *= scale; v.z *= scale; v.w *= scale;
        *(float4*)(Qs + r * 128 + c4 * 4) = v;
    }

    float acc[32];
#pragma unroll
    for (int z = 0; z < 32; z++) acc[z] = 0.0f;
    const int orow = tid >> 2;
    const int ocg  = tid & 3;

    if (tid < 64) { mrow[tid] = -1e30f; lrow[tid] = 0.0f; }
    __syncthreads();

    const int sx = tid & 15;
    const int sy = tid >> 4;
    const int ntiles = qt + 1;

    for (int kt = 0; kt < ntiles; kt++) {
        const int kn = kt * 64;
#pragma unroll
        for (int t = 0; t < 8; t++) {
            int idx = tid + 256 * t;
            int d4  = idx >> 6;
            int n   = idx & 63;
            float4 v = *(const float4*)(g_K + (size_t)(kn + n) * KVDIM + kvh * HDIM + d4 * 4);
            Kst[(d4 * 4 + 0) * 64 + n] = v.x;
            Kst[(d4 * 4 + 1) * 64 + n] = v.y;
            Kst[(d4 * 4 + 2) * 64 + n] = v.z;
            Kst[(d4 * 4 + 3) * 64 + n] = v.w;
        }
#pragma unroll
        for (int t = 0; t < 8; t++) {
            int idx = tid + 256 * t;
            int r   = idx >> 5;
            int c4  = idx & 31;
            *(float4*)(Vs + r * 128 + c4 * 4) =
                *(const float4*)(g_V + (size_t)(kn + r) * KVDIM + kvh * HDIM + c4 * 4);
        }
        __syncthreads();

        float sacc[4][4];
#pragma unroll
        for (int i = 0; i < 4; i++)
#pragma unroll
            for (int j = 0; j < 4; j++) sacc[i][j] = 0.0f;

#pragma unroll 8
        for (int d = 0; d < 128; d += 4) {
            float4 av[4], bvv[4];
#pragma unroll
            for (int i = 0; i < 4; i++)
                av[i] = *(const float4*)(Qs + (sy * 4 + i) * 128 + d);
#pragma unroll
            for (int e = 0; e < 4; e++)
                bvv[e] = *(const float4*)(Kst + (d + e) * 64 + sx * 4);
#pragma unroll
            for (int i = 0; i < 4; i++) {
                float ae[4] = {av[i].x, av[i].y, av[i].z, av[i].w};
#pragma unroll
                for (int e = 0; e < 4; e++) {
                    sacc[i][0] = fmaf(ae[e], bvv[e].x, sacc[i][0]);
                    sacc[i][1] = fmaf(ae[e], bvv[e].y, sacc[i][1]);
                    sacc[i][2] = fmaf(ae[e], bvv[e].z, sacc[i][2]);
                    sacc[i][3] = fmaf(ae[e], bvv[e].w, sacc[i][3]);
                }
            }
        }

        const bool diag = (kt == qt);
#pragma unroll
        for (int i = 0; i < 4; i++) {
            int qr = sy * 4 + i;
#pragma unroll
            for (int j = 0; j < 4; j++) {
                int kc = sx * 4 + j;
                float v = sacc[i][j];
                if (diag && kc > qr) v = -1e30f;
                Ss[qr * 65 + kc] = v;
            }
        }
        __syncthreads();

        if (tid < 64) {
            int r = tid;
            float m_old = mrow[r];
            float mx = m_old;
            for (int k = 0; k < 64; k++) mx = fmaxf(mx, Ss[r * 65 + k]);
            float a = expf(m_old - mx);
            float sum = 0.0f;
            for (int k = 0; k < 64; k++) {
                float p = expf(Ss[r * 65 + k] - mx);
                Ss[r * 65 + k] = p;
                sum += p;
            }
            lrow[r] = lrow[r] * a + sum;
            mrow[r] = mx;
            arow[r] = a;
        }
        __syncthreads();

        {
            float a = arow[orow];
#pragma unroll
            for (int z = 0; z < 32; z++) acc[z] *= a;
        }
#pragma unroll 4
        for (int kk = 0; kk < 64; kk++) {
            float p = Ss[orow * 65 + kk];
            const float4* vp = (const float4*)(Vs + kk * 128 + ocg * 32);
#pragma unroll
            for (int j4 = 0; j4 < 8; j4++) {
                float4 v = vp[j4];
                acc[j4 * 4 + 0] = fmaf(p, v.x, acc[j4 * 4 + 0]);
                acc[j4 * 4 + 1] = fmaf(p, v.y, acc[j4 * 4 + 1]);
                acc[j4 * 4 + 2] = fmaf(p, v.z, acc[j4 * 4 + 2]);
                acc[j4 * 4 + 3] = fmaf(p, v.w, acc[j4 * 4 + 3]);
            }
        }
        __syncthreads();
    }

    const float inv_l = 1.0f / lrow[orow];
    float* op = g_AO + (size_t)(qm + orow) * HID + h * HDIM + ocg * 32;
#pragma unroll
    for (int j4 = 0; j4 < 8; j4++) {
        float4 o;
        o.x = acc[j4 * 4 + 0] * inv_l;
        o.y = acc[j4 * 4 + 1] * inv_l;
        o.z = acc[j4 * 4 + 2] * inv_l;
        o.w = acc[j4 * 4 + 3] * inv_l;
        *(float4*)(op + j4 * 4) = o;
    }
}

// ============================================================
// launch
// ============================================================
extern "C" void kernel_launch(void* const* d_in, const int* in_sizes, int n_in,
                              void* d_out, int out_size)
{
    const float* hs  = (const float*)d_in[0];
    const int*   pos = (const int*)  d_in[1];
    const float* Wq  = (const float*)d_in[2];
    const float* bq  = (const float*)d_in[3];
    const float* Wk  = (const float*)d_in[4];
    const float* bk  = (const float*)d_in[5];
    const float* Wv  = (const float*)d_in[6];
    const float* bv  = (const float*)d_in[7];
    const float* Wo  = (const float*)d_in[8];
    float* out = (float*)d_out;

    void *qp, *kp, *vp, *aop;
    void *ah, *al, *aoh, *aol;
    void *wqh, *wql, *wkh, *wkl, *wvh, *wvl, *woh, *wol;
    cudaGetSymbolAddress(&qp,  g_Q);
    cudaGetSymbolAddress(&kp,  g_K);
    cudaGetSymbolAddress(&vp,  g_V);
    cudaGetSymbolAddress(&aop, g_AO);
    cudaGetSymbolAddress(&ah,  g_Ah);  cudaGetSymbolAddress(&al,  g_Al);
    cudaGetSymbolAddress(&aoh, g_AOh); cudaGetSymbolAddress(&aol, g_AOl);
    cudaGetSymbolAddress(&wqh, g_Wqh); cudaGetSymbolAddress(&wql, g_Wql);
    cudaGetSymbolAddress(&wkh, g_Wkh); cudaGetSymbolAddress(&wkl, g_Wkl);
    cudaGetSymbolAddress(&wvh, g_Wvh); cudaGetSymbolAddress(&wvl, g_Wvl);
    cudaGetSymbolAddress(&woh, g_Woh); cudaGetSymbolAddress(&wol, g_Wol);

    cudaFuncSetAttribute(attn_kernel,
                         cudaFuncAttributeMaxDynamicSharedMemorySize,
                         ATTN_SMEM_BYTES);
    cudaFuncSetAttribute(hgemm,
                         cudaFuncAttributeMaxDynamicSharedMemorySize,
                         GT_SMEM);

    // ---- bf16 hi/lo conversions ----
    auto cvt = [](const float* s, void* h, void* l, int n) {
        int n4 = n / 4;
        cvt_split<<<(n4 + 255) / 256, 256>>>(s, (__nv_bfloat16*)h,
                                             (__nv_bfloat16*)l, n4);
    };
    cvt(hs, ah, al, S_LEN * HID);
    cvt(Wq, wqh, wql, HID * HID);
    cvt(Wk, wkh, wkl, KVDIM * HID);
    cvt(Wv, wvh, wvl, KVDIM * HID);
    cvt(Wo, woh, wol, HID * HID);

    rope_table<<<S_LEN, 64>>>(pos);

    // ---- QKV projections (HMMA) ----
    hgemm<<<dim3(HID / 128,   S_LEN / 128), 256, GT_SMEM>>>(
        (__nv_bfloat16*)ah, (__nv_bfloat16*)al,
        (__nv_bfloat16*)wqh, (__nv_bfloat16*)wql, bq, (float*)qp, HID);
    hgemm<<<dim3(KVDIM / 128, S_LEN / 128), 256, GT_SMEM>>>(
        (__nv_bfloat16*)ah, (__nv_bfloat16*)al,
        (__nv_bfloat16*)wkh, (__nv_bfloat16*)wkl, bk, (float*)kp, KVDIM);
    hgemm<<<dim3(KVDIM / 128, S_LEN / 128), 256, GT_SMEM>>>(
        (__nv_bfloat16*)ah, (__nv_bfloat16*)al,
        (__nv_bfloat16*)wvh, (__nv_bfloat16*)wvl, bv, (float*)vp, KVDIM);

    rope_apply<<<dim3(S_LEN, NHEADS + NKV), 64>>>();

    attn_kernel<<<dim3(S_LEN / 64, NHEADS), 256, ATTN_SMEM_BYTES>>>();

    // ---- output projection ----
    cvt((const float*)aop, aoh, aol, S_LEN * HID);
    hgemm<<<dim3(HID / 128, S_LEN / 128), 256, GT_SMEM>>>(
        (__nv_bfloat16*)aoh, (__nv_bfloat16*)aol,
        (__nv_bfloat16*)woh, (__nv_bfloat16*)wol, nullptr, out, HID);
}